// round 3
// baseline (speedup 1.0000x reference)
#include <cuda_runtime.h>
#include <cstdint>

#define L 4096
#define NB 4

// One fused persistent kernel. 1184 blocks x 256 threads, grid-stride over
// 4096 work items of 128 KB each (total 512 MB of pure stores).
//
// Item types:
//   item in [0, 2048): channels 4..7 ("column" channels: value = f(col)).
//     item -> (c2 = channel-4, chunk of 256 float4-cols, slice of 32 rows).
//     Each thread decodes its 4 seq ids -> one float4, then streams 32
//     STG.128 down the rows (stride 16 KB). Zero loads in inner loop.
//   item in [2048, 4096): channels 0..3 ("row" channels: value = f(row)).
//     item -> 8 consecutive global rows; per row one seq decode, then
//     4 broadcast float4 stores per thread (full 16 KB row).
//
// seq_ids dtype (int32 vs int64) is detected per block: if int64 with values
// 0..3, the odd 32-bit words are all zero; 256 samples -> FP prob 4^-256.
__global__ void __launch_bounds__(256, 8)
fused_kernel(const int* __restrict__ w,            // seq_ids as 32-bit words
             const float* __restrict__ tab,        // base_table (4x4)
             float4* __restrict__ out) {
    __shared__ int s_nonzero_odd;
    const int tid = threadIdx.x;

    // ---- dtype detection (reads stay within the 16 KB int32 footprint) ----
    if (tid == 0) s_nonzero_odd = 0;
    __syncthreads();
    if (w[2 * tid + 1] != 0) atomicOr(&s_nonzero_odd, 1);
    __syncthreads();
    const int sh = (s_nonzero_odd == 0) ? 1 : 0;   // element x at word x<<sh

    // ---- grid-stride over work items ----
    for (unsigned item = blockIdx.x; item < 4096u; item += gridDim.x) {
        if (item < 2048u) {
            const int c2    = item >> 9;           // 0..3 (channel - 4)
            const int sub   = item & 511;
            const int chunk = sub & 3;             // 0..3: 256-float4 col chunk
            const int slice = sub >> 2;            // 0..127: 32-row slice

            const int x = ((chunk << 8) + tid) << 2;   // first of 4 columns
            const float4 v = make_float4(tab[(w[(x    ) << sh] << 2) + c2],
                                         tab[(w[(x + 1) << sh] << 2) + c2],
                                         tab[(w[(x + 2) << sh] << 2) + c2],
                                         tab[(w[(x + 3) << sh] << 2) + c2]);

            float4* p = out
                      + (((size_t)(4 + c2) << 12) + ((size_t)slice << 5)) * 1024
                      + (chunk << 8) + tid;
            #pragma unroll 8
            for (int i = 0; i < 32; i++) {
                __stcs(p, v);
                p += 1024;                         // next row, same column
            }
        } else {
            const unsigned row0 = (item - 2048u) << 3;   // 8 global rows
            #pragma unroll 1
            for (int r = 0; r < 8; r++) {
                const unsigned row = row0 + r;           // row = c*4096 + i
                const int c = row >> 12;
                const int i = row & 4095;
                const float s = tab[(w[i << sh] << 2) + c];
                const float4 v = make_float4(s, s, s, s);
                float4* o = out + (size_t)row * 1024 + tid;
                #pragma unroll
                for (int k = 0; k < 4; k++)
                    __stcs(o + k * 256, v);
            }
        }
    }
}

extern "C" void kernel_launch(void* const* d_in, const int* in_sizes, int n_in,
                              void* d_out, int out_size) {
    const int*   seq        = (const int*)d_in[0];
    const float* base_table = (const float*)d_in[1];

    fused_kernel<<<1184, 256>>>(seq, base_table, (float4*)d_out);
}

// round 4
// speedup vs baseline: 1.0502x; 1.0502x over previous
#include <cuda_runtime.h>
#include <cstdint>

#define L 4096
#define NB 4

// Scratch (no device allocation allowed in kernel_launch)
__device__ float g_rows[NB * L];   // g_rows[c*L + x] = base_table[seq[x]*4 + c]

// ---------------------------------------------------------------------------
// Prep: 32 blocks x 128 threads. Block b decodes elements [b*128, b*128+128).
// dtype detection per block: sample 64 odd 32-bit words among the first 2048
// elements (int64 with values 0..3 -> all zero; int32 -> ~surely nonzero).
// All detection reads stay within the 16 KB int32 footprint.
// ---------------------------------------------------------------------------
__global__ void prep_kernel(const int* __restrict__ w,
                            const float* __restrict__ tab) {
    __shared__ int s_nonzero_odd;
    const int tid = threadIdx.x;
    const int b   = blockIdx.x;

    if (tid == 0) s_nonzero_odd = 0;
    __syncthreads();

    if (tid < 64) {
        const int k = b * 64 + tid;            // k in [0, 2048)
        if (w[2 * k + 1] != 0) atomicOr(&s_nonzero_odd, 1);
    }
    __syncthreads();
    const int sh = (s_nonzero_odd == 0) ? 1 : 0;

    const int i = b * 128 + tid;               // element index
    const int s = w[i << sh];
    #pragma unroll
    for (int c = 0; c < NB; c++) {
        g_rows[c * L + i] = tab[s * NB + c];
    }
}

// ---------------------------------------------------------------------------
// Fill (identical to R2 best): 2048 blocks x 256 threads, 64 STG.128/thread.
//
// Blocks [0,1024): channels 4..7 (value depends on column only).
//   block -> (c2, chunk of 256 float4 columns, slice of 64 rows).
//   Thread registers its column float4 ONCE (L2-hit), then streams 64 stores
//   down the rows (stride 16 KB). No loads in the inner loop.
//
// Blocks [1024,2048): channels 0..3 (value depends on row only).
//   block -> 16 consecutive global rows; per row one broadcast scalar load,
//   4 broadcast float4 stores per thread. row == index into g_rows directly.
// ---------------------------------------------------------------------------
__global__ void __launch_bounds__(256, 8)
fill_kernel(float4* __restrict__ out) {
    const int tid = threadIdx.x;
    const unsigned b = blockIdx.x;

    if (b < 1024u) {
        const int c2    = b >> 8;          // 0..3  (channel - 4)
        const int sub   = b & 255;
        const int chunk = sub & 3;         // 0..3 : 256-float4 column chunk
        const int slice = sub >> 2;        // 0..63: 64-row slice

        const float4 v = ((const float4*)&g_rows[c2 << 12])[(chunk << 8) + tid];

        float4* p = out
                  + (((size_t)(4 + c2) << 12) + ((size_t)slice << 6)) * 1024
                  + (chunk << 8) + tid;
        #pragma unroll 8
        for (int i = 0; i < 64; i++) {
            p[0] = v;
            p += 1024;                     // next row, same column
        }
    } else {
        const unsigned row0 = (b - 1024u) << 4;   // 16 rows, global rows 0..16383
        #pragma unroll 1
        for (int r = 0; r < 16; r++) {
            const unsigned row = row0 + r;
            const float s = g_rows[row];          // row == c*4096 + i
            const float4 v = make_float4(s, s, s, s);
            float4* o = out + (size_t)row * 1024 + tid;
            #pragma unroll
            for (int k = 0; k < 4; k++)
                o[k * 256] = v;
        }
    }
}

extern "C" void kernel_launch(void* const* d_in, const int* in_sizes, int n_in,
                              void* d_out, int out_size) {
    const int*   seq        = (const int*)d_in[0];
    const float* base_table = (const float*)d_in[1];

    prep_kernel<<<32, 128>>>(seq, base_table);
    fill_kernel<<<2048, 256>>>((float4*)d_out);
}